// round 7
// baseline (speedup 1.0000x reference)
#include <cuda_runtime.h>

// Problem constants (fixed shapes from setup_inputs)
#define NN 10000          // nodes
#define NE 160000         // edges
#define NG 64             // replicas B*S = 2*32
#define NH 32             // hidden dim

// ---- device scratch (static, no allocations) ----
__device__ float g_deg[NN];
__device__ float g_dinv[NN];
__device__ int   g_cnt[NN];          // histogram, then reused as scatter cursor
__device__ int   g_rowptr[NN + 1];
__device__ int   g_col[NE];
__device__ float g_val[NE];
__device__ float g_xT[NG * NN];      // x transposed to [n][g]
__device__ float g_tT[NG * NN];      // layer-1 output (post-MLP) [n][g]
__device__ float g_oT[NG * NN];      // layer-2 output [n][g]

// ---------------------------------------------------------------- init
__global__ void k_init() {
    int i = blockIdx.x * blockDim.x + threadIdx.x;
    if (i < NN) { g_deg[i] = 0.0f; g_cnt[i] = 0; }
}

// degree (weighted, by dst) + edge count histogram
__global__ void k_degcnt(const int* __restrict__ ei, const float* __restrict__ w) {
    int e = blockIdx.x * blockDim.x + threadIdx.x;
    if (e < NE) {
        int d = ei[NE + e];           // dst row of edge_index
        atomicAdd(&g_deg[d], w[e]);
        atomicAdd(&g_cnt[d], 1);
    }
}

// dinv = rsqrt(deg + 1)   (self-loop weight 1 makes deg > 0 always)
__global__ void k_dinv() {
    int i = blockIdx.x * blockDim.x + threadIdx.x;
    if (i < NN) g_dinv[i] = rsqrtf(g_deg[i] + 1.0f);
}

// single-block exclusive scan of g_cnt -> g_rowptr; zero cursor
__global__ void k_scan() {
    __shared__ int part[1024];
    int tid = threadIdx.x;
    const int CH = (NN + 1023) / 1024;  // 10
    int base = tid * CH;
    int sum = 0;
#pragma unroll
    for (int i = 0; i < CH; i++) {
        int idx = base + i;
        if (idx < NN) sum += g_cnt[idx];
    }
    part[tid] = sum;
    __syncthreads();
    // Hillis-Steele inclusive scan over 1024 partials
    for (int off = 1; off < 1024; off <<= 1) {
        int v = (tid >= off) ? part[tid - off] : 0;
        __syncthreads();
        if (tid >= off) part[tid] += v;
        __syncthreads();
    }
    int run = (tid == 0) ? 0 : part[tid - 1];
#pragma unroll
    for (int i = 0; i < CH; i++) {
        int idx = base + i;
        if (idx < NN) {
            g_rowptr[idx] = run;
            run += g_cnt[idx];
            g_cnt[idx] = 0;           // reuse as scatter cursor
        }
    }
    if (tid == 0) g_rowptr[NN] = NE;
}

// scatter edges into CSR (by dst), precompute normalized edge values
__global__ void k_build(const int* __restrict__ ei, const float* __restrict__ w) {
    int e = blockIdx.x * blockDim.x + threadIdx.x;
    if (e < NE) {
        int s = ei[e];
        int d = ei[NE + e];
        int pos = atomicAdd(&g_cnt[d], 1);
        int idx = g_rowptr[d] + pos;
        g_col[idx] = s;
        g_val[idx] = g_dinv[s] * w[e] * g_dinv[d];
    }
}

// transpose x [g][n] -> g_xT [n][g], tiled for full coalescing
__global__ void k_xpose_in(const float* __restrict__ x) {
    __shared__ float tile[32][33];
    int n0 = blockIdx.x * 32;
    int g0 = blockIdx.y * 32;
    for (int r = threadIdx.y; r < 32; r += 8) {
        int g = g0 + r, n = n0 + threadIdx.x;
        if (n < NN) tile[r][threadIdx.x] = x[g * NN + n];
    }
    __syncthreads();
    for (int r = threadIdx.y; r < 32; r += 8) {
        int n = n0 + r, g = g0 + threadIdx.x;
        if (n < NN) g_xT[n * NG + g] = tile[threadIdx.x][r];
    }
}

// SpMV pass 1 over x, fused with the per-scalar MLP f(s)=sum_h relu(s*W1+b1)*W2
// block: (64 replicas, 4 nodes)
__global__ void k_spmv1(const float* __restrict__ W1, const float* __restrict__ b1,
                        const float* __restrict__ W2) {
    __shared__ float sw1[NH], sb1[NH], sw2[NH];
    int t = threadIdx.y * 64 + threadIdx.x;
    if (t < NH) { sw1[t] = W1[t]; sb1[t] = b1[t]; sw2[t] = W2[t]; }
    __syncthreads();

    int g = threadIdx.x;
    int n = blockIdx.x * blockDim.y + threadIdx.y;
    if (n >= NN) return;

    float dv = g_dinv[n];
    float acc = dv * dv * g_xT[n * NG + g];
    int beg = g_rowptr[n], end = g_rowptr[n + 1];
    int j = beg;
    for (; j + 4 <= end; j += 4) {
        int   c0 = g_col[j],   c1 = g_col[j + 1], c2 = g_col[j + 2], c3 = g_col[j + 3];
        float v0 = g_val[j],   v1 = g_val[j + 1], v2 = g_val[j + 2], v3 = g_val[j + 3];
        float x0 = g_xT[c0 * NG + g], x1 = g_xT[c1 * NG + g];
        float x2 = g_xT[c2 * NG + g], x3 = g_xT[c3 * NG + g];
        acc = fmaf(v0, x0, fmaf(v1, x1, fmaf(v2, x2, fmaf(v3, x3, acc))));
    }
    for (; j < end; j++) acc = fmaf(g_val[j], g_xT[g_col[j] * NG + g], acc);

    // pointwise MLP: t = sum_h relu(acc*W1[h]+b1[h]) * W2[h]
    float s = acc, out = 0.0f;
#pragma unroll
    for (int h = 0; h < NH; h++) {
        float a = fmaf(s, sw1[h], sb1[h]);
        a = fmaxf(a, 0.0f);
        out = fmaf(a, sw2[h], out);
    }
    g_tT[n * NG + g] = out;
}

// SpMV pass 2 over t, + b2
__global__ void k_spmv2(const float* __restrict__ b2) {
    int g = threadIdx.x;
    int n = blockIdx.x * blockDim.y + threadIdx.y;
    if (n >= NN) return;

    float dv = g_dinv[n];
    float acc = dv * dv * g_tT[n * NG + g];
    int beg = g_rowptr[n], end = g_rowptr[n + 1];
    int j = beg;
    for (; j + 4 <= end; j += 4) {
        int   c0 = g_col[j],   c1 = g_col[j + 1], c2 = g_col[j + 2], c3 = g_col[j + 3];
        float v0 = g_val[j],   v1 = g_val[j + 1], v2 = g_val[j + 2], v3 = g_val[j + 3];
        float x0 = g_tT[c0 * NG + g], x1 = g_tT[c1 * NG + g];
        float x2 = g_tT[c2 * NG + g], x3 = g_tT[c3 * NG + g];
        acc = fmaf(v0, x0, fmaf(v1, x1, fmaf(v2, x2, fmaf(v3, x3, acc))));
    }
    for (; j < end; j++) acc = fmaf(g_val[j], g_tT[g_col[j] * NG + g], acc);

    g_oT[n * NG + g] = acc + b2[0];
}

// transpose back [n][g] -> out [g][n], fusing the observation mask.
// mask is int32 on device (harness materializes bool as int32).
__global__ void k_out(const float* __restrict__ x, const int* __restrict__ mask,
                      float* __restrict__ out) {
    __shared__ float tile[32][33];
    int n0 = blockIdx.x * 32;
    int g0 = blockIdx.y * 32;
    for (int r = threadIdx.y; r < 32; r += 8) {
        int n = n0 + r;
        if (n < NN) tile[r][threadIdx.x] = g_oT[n * NG + g0 + threadIdx.x];
    }
    __syncthreads();
    for (int r = threadIdx.y; r < 32; r += 8) {
        int g = g0 + r;
        int n = n0 + threadIdx.x;
        if (n < NN) {
            int idx = g * NN + n;
            out[idx] = (mask[idx] != 0) ? x[idx] : tile[threadIdx.x][r];
        }
    }
}

extern "C" void kernel_launch(void* const* d_in, const int* in_sizes, int n_in,
                              void* d_out, int out_size) {
    const float* x    = (const float*)d_in[0];
    const int*   mask = (const int*)d_in[1];       // bool materialized as int32
    const int*   ei   = (const int*)d_in[2];       // (2, E)
    const float* w    = (const float*)d_in[3];
    const float* W1   = (const float*)d_in[4];
    const float* b1   = (const float*)d_in[5];
    const float* W2   = (const float*)d_in[6];
    const float* b2   = (const float*)d_in[7];
    float*       out  = (float*)d_out;

    k_init  <<<(NN + 255) / 256, 256>>>();
    k_degcnt<<<(NE + 255) / 256, 256>>>(ei, w);
    k_dinv  <<<(NN + 255) / 256, 256>>>();
    k_scan  <<<1, 1024>>>();
    k_build <<<(NE + 255) / 256, 256>>>(ei, w);

    dim3 tb(32, 8);
    dim3 tg((NN + 31) / 32, NG / 32);
    k_xpose_in<<<tg, tb>>>(x);

    dim3 sb(64, 4);
    k_spmv1<<<NN / 4, sb>>>(W1, b1, W2);
    k_spmv2<<<NN / 4, sb>>>(b2);

    k_out<<<tg, tb>>>(x, mask, out);
}

// round 8
// speedup vs baseline: 1.0795x; 1.0795x over previous
#include <cuda_runtime.h>

// Problem constants (fixed shapes from setup_inputs)
#define NN 10000          // nodes
#define NE 160000         // edges
#define NG 64             // replicas B*S = 2*32
#define NQ 16             // NG/4 float4 lanes per node
#define NH 32             // hidden dim

// ---- device scratch (static, no allocations) ----
__device__ float g_deg[NN];
__device__ float g_dinv[NN];
__device__ int   g_cnt[NN];          // histogram, then reused as scatter cursor
__device__ int   g_rowptr[NN + 1];
__device__ int   g_col[NE];
__device__ float g_val[NE];
__device__ float4 g_xT[NN * NQ];     // x transposed to [n][g], viewed as float4
__device__ float4 g_tT[NN * NQ];     // layer-1 output (post-MLP) [n][g]
__device__ float4 g_oT[NN * NQ];     // layer-2 output [n][g]

// ---------------------------------------------------------------- init
__global__ void k_init() {
    int i = blockIdx.x * blockDim.x + threadIdx.x;
    if (i < NN) { g_deg[i] = 0.0f; g_cnt[i] = 0; }
}

// degree (weighted, by dst) + edge count histogram
__global__ void k_degcnt(const int* __restrict__ ei, const float* __restrict__ w) {
    int e = blockIdx.x * blockDim.x + threadIdx.x;
    if (e < NE) {
        int d = ei[NE + e];           // dst row of edge_index
        atomicAdd(&g_deg[d], w[e]);
        atomicAdd(&g_cnt[d], 1);
    }
}

// fused: dinv = rsqrt(deg + 1), then shuffle-based exclusive scan of g_cnt.
// single block, 1024 threads, CH=10 elements/thread, 2 barriers total.
__global__ void __launch_bounds__(1024) k_scan() {
    const int tid  = threadIdx.x;
    const int lane = tid & 31;
    const int wid  = tid >> 5;

    // dinv (independent of the scan; self-loop weight 1 => deg+1 > 0)
    for (int i = tid; i < NN; i += 1024)
        g_dinv[i] = rsqrtf(g_deg[i] + 1.0f);

    const int CH = 10;                 // 1024*10 >= 10000
    int base = tid * CH;
    int cnt[CH];
    int sum = 0;
#pragma unroll
    for (int i = 0; i < CH; i++) {
        int idx = base + i;
        cnt[i] = (idx < NN) ? g_cnt[idx] : 0;
        sum += cnt[i];
    }

    // warp-inclusive scan of per-thread sums
    int incl = sum;
#pragma unroll
    for (int o = 1; o < 32; o <<= 1) {
        int v = __shfl_up_sync(0xFFFFFFFFu, incl, o);
        if (lane >= o) incl += v;
    }

    __shared__ int warpsum[32];
    if (lane == 31) warpsum[wid] = incl;
    __syncthreads();

    if (wid == 0) {
        int v = warpsum[lane];
        int s = v;
#pragma unroll
        for (int o = 1; o < 32; o <<= 1) {
            int u = __shfl_up_sync(0xFFFFFFFFu, s, o);
            if (lane >= o) s += u;
        }
        warpsum[lane] = s;             // inclusive warp-sum scan
    }
    __syncthreads();

    int run = (wid ? warpsum[wid - 1] : 0) + (incl - sum);  // exclusive prefix
#pragma unroll
    for (int i = 0; i < CH; i++) {
        int idx = base + i;
        if (idx < NN) {
            g_rowptr[idx] = run;
            run += cnt[i];
            g_cnt[idx] = 0;            // reuse as scatter cursor
        }
    }
    if (tid == 0) g_rowptr[NN] = NE;
}

// scatter edges into CSR (by dst), precompute normalized edge values
__global__ void k_build(const int* __restrict__ ei, const float* __restrict__ w) {
    int e = blockIdx.x * blockDim.x + threadIdx.x;
    if (e < NE) {
        int s = ei[e];
        int d = ei[NE + e];
        int pos = atomicAdd(&g_cnt[d], 1);
        int idx = g_rowptr[d] + pos;
        g_col[idx] = s;
        g_val[idx] = g_dinv[s] * w[e] * g_dinv[d];
    }
}

// transpose x [g][n] -> g_xT [n][g], tiled for full coalescing
__global__ void k_xpose_in(const float* __restrict__ x) {
    __shared__ float tile[32][33];
    int n0 = blockIdx.x * 32;
    int g0 = blockIdx.y * 32;
    float* xT = (float*)g_xT;
    for (int r = threadIdx.y; r < 32; r += 8) {
        int g = g0 + r, n = n0 + threadIdx.x;
        if (n < NN) tile[r][threadIdx.x] = x[g * NN + n];
    }
    __syncthreads();
    for (int r = threadIdx.y; r < 32; r += 8) {
        int n = n0 + r, g = g0 + threadIdx.x;
        if (n < NN) xT[n * NG + g] = tile[threadIdx.x][r];
    }
}

__device__ __forceinline__ float4 f4fma(float s, float4 a, float4 acc) {
    acc.x = fmaf(s, a.x, acc.x);
    acc.y = fmaf(s, a.y, acc.y);
    acc.z = fmaf(s, a.z, acc.z);
    acc.w = fmaf(s, a.w, acc.w);
    return acc;
}

// SpMV pass 1 over x (float4 over replicas), fused with the per-scalar MLP
// f(s)=sum_h relu(s*W1[h]+b1[h])*W2[h].   block: (16 quads, 16 nodes)
__global__ void __launch_bounds__(256) k_spmv1(const float* __restrict__ W1,
                                               const float* __restrict__ b1,
                                               const float* __restrict__ W2) {
    __shared__ float sw1[NH], sb1[NH], sw2[NH];
    int t = threadIdx.y * NQ + threadIdx.x;
    if (t < NH) { sw1[t] = W1[t]; sb1[t] = b1[t]; sw2[t] = W2[t]; }
    __syncthreads();

    int q = threadIdx.x;                          // 0..15 (4 replicas each)
    int n = blockIdx.x * blockDim.y + threadIdx.y;
    if (n >= NN) return;

    float dv = g_dinv[n];
    float dd = dv * dv;
    float4 xv = g_xT[n * NQ + q];
    float4 acc = make_float4(dd * xv.x, dd * xv.y, dd * xv.z, dd * xv.w);

    int beg = g_rowptr[n], end = g_rowptr[n + 1];
    int j = beg;
    for (; j + 4 <= end; j += 4) {
        int   c0 = g_col[j],   c1 = g_col[j + 1], c2 = g_col[j + 2], c3 = g_col[j + 3];
        float v0 = g_val[j],   v1 = g_val[j + 1], v2 = g_val[j + 2], v3 = g_val[j + 3];
        float4 a0 = g_xT[c0 * NQ + q], a1 = g_xT[c1 * NQ + q];
        float4 a2 = g_xT[c2 * NQ + q], a3 = g_xT[c3 * NQ + q];
        acc = f4fma(v0, a0, acc);
        acc = f4fma(v1, a1, acc);
        acc = f4fma(v2, a2, acc);
        acc = f4fma(v3, a3, acc);
    }
    for (; j < end; j++)
        acc = f4fma(g_val[j], g_xT[g_col[j] * NQ + q], acc);

    // pointwise MLP on each of the 4 replica scalars
    float4 res = make_float4(0.f, 0.f, 0.f, 0.f);
#pragma unroll
    for (int h = 0; h < NH; h++) {
        float w1 = sw1[h], bb = sb1[h], w2 = sw2[h];
        res.x = fmaf(fmaxf(fmaf(acc.x, w1, bb), 0.f), w2, res.x);
        res.y = fmaf(fmaxf(fmaf(acc.y, w1, bb), 0.f), w2, res.y);
        res.z = fmaf(fmaxf(fmaf(acc.z, w1, bb), 0.f), w2, res.z);
        res.w = fmaf(fmaxf(fmaf(acc.w, w1, bb), 0.f), w2, res.w);
    }
    g_tT[n * NQ + q] = res;
}

// SpMV pass 2 over t, + b2
__global__ void __launch_bounds__(256) k_spmv2(const float* __restrict__ b2) {
    int q = threadIdx.x;
    int n = blockIdx.x * blockDim.y + threadIdx.y;
    if (n >= NN) return;

    float dv = g_dinv[n];
    float dd = dv * dv;
    float4 tv = g_tT[n * NQ + q];
    float4 acc = make_float4(dd * tv.x, dd * tv.y, dd * tv.z, dd * tv.w);

    int beg = g_rowptr[n], end = g_rowptr[n + 1];
    int j = beg;
    for (; j + 4 <= end; j += 4) {
        int   c0 = g_col[j],   c1 = g_col[j + 1], c2 = g_col[j + 2], c3 = g_col[j + 3];
        float v0 = g_val[j],   v1 = g_val[j + 1], v2 = g_val[j + 2], v3 = g_val[j + 3];
        float4 a0 = g_tT[c0 * NQ + q], a1 = g_tT[c1 * NQ + q];
        float4 a2 = g_tT[c2 * NQ + q], a3 = g_tT[c3 * NQ + q];
        acc = f4fma(v0, a0, acc);
        acc = f4fma(v1, a1, acc);
        acc = f4fma(v2, a2, acc);
        acc = f4fma(v3, a3, acc);
    }
    for (; j < end; j++)
        acc = f4fma(g_val[j], g_tT[g_col[j] * NQ + q], acc);

    float bb = b2[0];
    g_oT[n * NQ + q] = make_float4(acc.x + bb, acc.y + bb, acc.z + bb, acc.w + bb);
}

// transpose back [n][g] -> out [g][n], fusing the observation mask.
// mask is int32 on device (harness materializes bool as int32).
__global__ void k_out(const float* __restrict__ x, const int* __restrict__ mask,
                      float* __restrict__ out) {
    __shared__ float tile[32][33];
    int n0 = blockIdx.x * 32;
    int g0 = blockIdx.y * 32;
    const float* oT = (const float*)g_oT;
    for (int r = threadIdx.y; r < 32; r += 8) {
        int n = n0 + r;
        if (n < NN) tile[r][threadIdx.x] = oT[n * NG + g0 + threadIdx.x];
    }
    __syncthreads();
    for (int r = threadIdx.y; r < 32; r += 8) {
        int g = g0 + r;
        int n = n0 + threadIdx.x;
        if (n < NN) {
            int idx = g * NN + n;
            out[idx] = (mask[idx] != 0) ? x[idx] : tile[threadIdx.x][r];
        }
    }
}

extern "C" void kernel_launch(void* const* d_in, const int* in_sizes, int n_in,
                              void* d_out, int out_size) {
    const float* x    = (const float*)d_in[0];
    const int*   mask = (const int*)d_in[1];       // bool materialized as int32
    const int*   ei   = (const int*)d_in[2];       // (2, E)
    const float* w    = (const float*)d_in[3];
    const float* W1   = (const float*)d_in[4];
    const float* b1   = (const float*)d_in[5];
    const float* W2   = (const float*)d_in[6];
    const float* b2   = (const float*)d_in[7];
    float*       out  = (float*)d_out;

    k_init  <<<(NN + 255) / 256, 256>>>();
    k_degcnt<<<(NE + 255) / 256, 256>>>(ei, w);
    k_scan  <<<1, 1024>>>();                       // fused dinv + scan
    k_build <<<(NE + 255) / 256, 256>>>(ei, w);

    dim3 tb(32, 8);
    dim3 tg((NN + 31) / 32, NG / 32);
    k_xpose_in<<<tg, tb>>>(x);

    dim3 sb(NQ, 16);                               // 256 threads, 16 nodes/block
    k_spmv1<<<NN / 16, sb>>>(W1, b1, W2);
    k_spmv2<<<NN / 16, sb>>>(b2);

    k_out<<<tg, tb>>>(x, mask, out);
}

// round 9
// speedup vs baseline: 1.1296x; 1.0464x over previous
#include <cuda_runtime.h>

// Problem constants (fixed shapes from setup_inputs)
#define NN 10000          // nodes
#define NE 160000         // edges
#define NG 64             // replicas B*S = 2*32
#define NQ 16             // NG/4 float4 lanes per node
#define NH 32             // hidden dim

// ---- device scratch (static, no allocations; zero-init at module load) ----
__device__ float  g_deg[NN];        // zeroed by k_out of previous invocation
__device__ int    g_cnt[NN];        // histogram -> absolute scatter cursor
__device__ float  g_dinv[NN];
__device__ int    g_rowptr[NN + 1];
__device__ int2   g_cv[NE];         // packed {col, w bits}
__device__ float4 g_xT[NN * NQ];    // dinv-scaled x, node-major [n][g]
__device__ float4 g_tT[NN * NQ];    // dinv-scaled layer-1 output
__device__ float4 g_oT[NN * NQ];    // layer-2 output

// ------------------------------------------------------------ degree + count
// 4 edges/thread, vector loads for MLP=4. Requires g_deg/g_cnt pre-zeroed.
__global__ void k_degcnt(const int* __restrict__ ei, const float* __restrict__ w) {
    int e4 = blockIdx.x * blockDim.x + threadIdx.x;
    if (e4 >= NE / 4) return;
    int4   d = ((const int4*)(ei + NE))[e4];
    float4 v = ((const float4*)w)[e4];
    atomicAdd(&g_deg[d.x], v.x);
    atomicAdd(&g_deg[d.y], v.y);
    atomicAdd(&g_deg[d.z], v.z);
    atomicAdd(&g_deg[d.w], v.w);
    atomicAdd(&g_cnt[d.x], 1);
    atomicAdd(&g_cnt[d.y], 1);
    atomicAdd(&g_cnt[d.z], 1);
    atomicAdd(&g_cnt[d.w], 1);
}

// ------------------------------------------------- dinv + scan (single block)
// dinv = rsqrt(deg+1); shuffle scan of counts. g_cnt becomes the ABSOLUTE
// scatter cursor (init to rowptr), g_rowptr kept for the SpMV row loops.
__global__ void __launch_bounds__(1024) k_scan() {
    const int tid  = threadIdx.x;
    const int lane = tid & 31;
    const int wid  = tid >> 5;

    for (int i = tid; i < NN; i += 1024)
        g_dinv[i] = rsqrtf(g_deg[i] + 1.0f);

    const int CH = 10;                 // 1024*10 >= 10000
    int base = tid * CH;
    int cnt[CH];
    int sum = 0;
#pragma unroll
    for (int i = 0; i < CH; i++) {
        int idx = base + i;
        cnt[i] = (idx < NN) ? g_cnt[idx] : 0;
        sum += cnt[i];
    }

    int incl = sum;
#pragma unroll
    for (int o = 1; o < 32; o <<= 1) {
        int v = __shfl_up_sync(0xFFFFFFFFu, incl, o);
        if (lane >= o) incl += v;
    }

    __shared__ int warpsum[32];
    if (lane == 31) warpsum[wid] = incl;
    __syncthreads();
    if (wid == 0) {
        int s = warpsum[lane];
#pragma unroll
        for (int o = 1; o < 32; o <<= 1) {
            int u = __shfl_up_sync(0xFFFFFFFFu, s, o);
            if (lane >= o) s += u;
        }
        warpsum[lane] = s;
    }
    __syncthreads();

    int run = (wid ? warpsum[wid - 1] : 0) + (incl - sum);
#pragma unroll
    for (int i = 0; i < CH; i++) {
        int idx = base + i;
        if (idx < NN) {
            g_rowptr[idx] = run;
            g_cnt[idx]    = run;       // absolute cursor for k_build
            run += cnt[i];
        }
    }
    if (tid == 0) g_rowptr[NN] = NE;
}

// --------------------------------------- fused: CSR scatter + scaled transpose
// blocks [0, BUILD_BLK): build (4 edges/thread, val = raw w, absolute cursor)
// blocks [BUILD_BLK, +626): transpose x -> g_xT with x~ = dinv[n]*x
#define BUILD_BLK 157                  // ceil(40000/256)
__global__ void k_build_xpose(const int* __restrict__ ei, const float* __restrict__ w,
                              const float* __restrict__ x) {
    if (blockIdx.x < BUILD_BLK) {
        int e4 = blockIdx.x * blockDim.x + threadIdx.x;
        if (e4 >= NE / 4) return;
        int4   s = ((const int4*)ei)[e4];
        int4   d = ((const int4*)(ei + NE))[e4];
        float4 v = ((const float4*)w)[e4];
        int i0 = atomicAdd(&g_cnt[d.x], 1);
        int i1 = atomicAdd(&g_cnt[d.y], 1);
        int i2 = atomicAdd(&g_cnt[d.z], 1);
        int i3 = atomicAdd(&g_cnt[d.w], 1);
        g_cv[i0] = make_int2(s.x, __float_as_int(v.x));
        g_cv[i1] = make_int2(s.y, __float_as_int(v.y));
        g_cv[i2] = make_int2(s.z, __float_as_int(v.z));
        g_cv[i3] = make_int2(s.w, __float_as_int(v.w));
    } else {
        __shared__ float tile[32][33];
        int bx  = blockIdx.x - BUILD_BLK;   // 0..625
        int n0  = (bx % 313) * 32;
        int g0  = (bx / 313) * 32;
        int tx  = threadIdx.x & 31;
        int ty  = threadIdx.x >> 5;         // 0..7
        float* xT = (float*)g_xT;
        for (int r = ty; r < 32; r += 8) {
            int g = g0 + r, n = n0 + tx;
            if (n < NN) tile[r][tx] = x[g * NN + n];
        }
        __syncthreads();
        for (int r = ty; r < 32; r += 8) {
            int n = n0 + r, g = g0 + tx;
            if (n < NN) xT[n * NG + g] = g_dinv[n] * tile[tx][r];
        }
    }
}

__device__ __forceinline__ float4 f4fma(float s, float4 a, float4 acc) {
    acc.x = fmaf(s, a.x, acc.x);
    acc.y = fmaf(s, a.y, acc.y);
    acc.z = fmaf(s, a.z, acc.z);
    acc.w = fmaf(s, a.w, acc.w);
    return acc;
}

// ------------------------------------------- SpMV pass 1 + pointwise MLP
// acc = x~[n] + sum_e w_e * x~[src_e];  s = dinv[n]*acc;  t~ = dinv[n]*MLP(s)
__global__ void __launch_bounds__(256) k_spmv1(const float* __restrict__ W1,
                                               const float* __restrict__ b1,
                                               const float* __restrict__ W2) {
    __shared__ float sw1[NH], sb1[NH], sw2[NH];
    int t = threadIdx.y * NQ + threadIdx.x;
    if (t < NH) { sw1[t] = W1[t]; sb1[t] = b1[t]; sw2[t] = W2[t]; }
    __syncthreads();

    int q = threadIdx.x;
    int n = blockIdx.x * blockDim.y + threadIdx.y;
    if (n >= NN) return;

    float4 acc = g_xT[n * NQ + q];           // self-loop term (pre-scaled)
    int beg = g_rowptr[n], end = g_rowptr[n + 1];
    int j = beg;
    for (; j + 4 <= end; j += 4) {
        int2 c0 = g_cv[j],     c1 = g_cv[j + 1];
        int2 c2 = g_cv[j + 2], c3 = g_cv[j + 3];
        float4 a0 = g_xT[c0.x * NQ + q], a1 = g_xT[c1.x * NQ + q];
        float4 a2 = g_xT[c2.x * NQ + q], a3 = g_xT[c3.x * NQ + q];
        acc = f4fma(__int_as_float(c0.y), a0, acc);
        acc = f4fma(__int_as_float(c1.y), a1, acc);
        acc = f4fma(__int_as_float(c2.y), a2, acc);
        acc = f4fma(__int_as_float(c3.y), a3, acc);
    }
    for (; j < end; j++) {
        int2 c = g_cv[j];
        acc = f4fma(__int_as_float(c.y), g_xT[c.x * NQ + q], acc);
    }

    float dv = g_dinv[n];
    float4 s = make_float4(dv * acc.x, dv * acc.y, dv * acc.z, dv * acc.w);
    float4 res = make_float4(0.f, 0.f, 0.f, 0.f);
#pragma unroll
    for (int h = 0; h < NH; h++) {
        float w1 = sw1[h], bb = sb1[h], w2 = sw2[h];
        res.x = fmaf(fmaxf(fmaf(s.x, w1, bb), 0.f), w2, res.x);
        res.y = fmaf(fmaxf(fmaf(s.y, w1, bb), 0.f), w2, res.y);
        res.z = fmaf(fmaxf(fmaf(s.z, w1, bb), 0.f), w2, res.z);
        res.w = fmaf(fmaxf(fmaf(s.w, w1, bb), 0.f), w2, res.w);
    }
    // pre-scale for layer 2: t~ = dinv * t
    g_tT[n * NQ + q] = make_float4(dv * res.x, dv * res.y, dv * res.z, dv * res.w);
}

// ------------------------------------------- SpMV pass 2: out = dinv*acc + b2
__global__ void __launch_bounds__(256) k_spmv2(const float* __restrict__ b2) {
    int q = threadIdx.x;
    int n = blockIdx.x * blockDim.y + threadIdx.y;
    if (n >= NN) return;

    float4 acc = g_tT[n * NQ + q];
    int beg = g_rowptr[n], end = g_rowptr[n + 1];
    int j = beg;
    for (; j + 4 <= end; j += 4) {
        int2 c0 = g_cv[j],     c1 = g_cv[j + 1];
        int2 c2 = g_cv[j + 2], c3 = g_cv[j + 3];
        float4 a0 = g_tT[c0.x * NQ + q], a1 = g_tT[c1.x * NQ + q];
        float4 a2 = g_tT[c2.x * NQ + q], a3 = g_tT[c3.x * NQ + q];
        acc = f4fma(__int_as_float(c0.y), a0, acc);
        acc = f4fma(__int_as_float(c1.y), a1, acc);
        acc = f4fma(__int_as_float(c2.y), a2, acc);
        acc = f4fma(__int_as_float(c3.y), a3, acc);
    }
    for (; j < end; j++) {
        int2 c = g_cv[j];
        acc = f4fma(__int_as_float(c.y), g_tT[c.x * NQ + q], acc);
    }

    float dv = g_dinv[n], bb = b2[0];
    g_oT[n * NQ + q] = make_float4(fmaf(dv, acc.x, bb), fmaf(dv, acc.y, bb),
                                   fmaf(dv, acc.z, bb), fmaf(dv, acc.w, bb));
}

// ------------------ output transpose + mask merge + re-zero deg/cnt for next call
__global__ void k_out(const float* __restrict__ x, const int* __restrict__ mask,
                      float* __restrict__ out) {
    // re-establish the zeroed-scratch invariant (device globals start zeroed,
    // and every invocation ends with this kernel)
    int lin = (blockIdx.y * gridDim.x + blockIdx.x) * blockDim.x * blockDim.y
              + threadIdx.y * blockDim.x + threadIdx.x;
    if (lin < NN) { g_deg[lin] = 0.0f; g_cnt[lin] = 0; }

    __shared__ float tile[32][33];
    int n0 = blockIdx.x * 32;
    int g0 = blockIdx.y * 32;
    const float* oT = (const float*)g_oT;
    for (int r = threadIdx.y; r < 32; r += 8) {
        int n = n0 + r;
        if (n < NN) tile[r][threadIdx.x] = oT[n * NG + g0 + threadIdx.x];
    }
    __syncthreads();
    for (int r = threadIdx.y; r < 32; r += 8) {
        int g = g0 + r;
        int n = n0 + threadIdx.x;
        if (n < NN) {
            int idx = g * NN + n;
            out[idx] = (mask[idx] != 0) ? x[idx] : tile[threadIdx.x][r];
        }
    }
}

extern "C" void kernel_launch(void* const* d_in, const int* in_sizes, int n_in,
                              void* d_out, int out_size) {
    const float* x    = (const float*)d_in[0];
    const int*   mask = (const int*)d_in[1];       // bool materialized as int32
    const int*   ei   = (const int*)d_in[2];       // (2, E)
    const float* w    = (const float*)d_in[3];
    const float* W1   = (const float*)d_in[4];
    const float* b1   = (const float*)d_in[5];
    const float* W2   = (const float*)d_in[6];
    const float* b2   = (const float*)d_in[7];
    float*       out  = (float*)d_out;

    k_degcnt<<<(NE / 4 + 255) / 256, 256>>>(ei, w);
    k_scan  <<<1, 1024>>>();
    k_build_xpose<<<BUILD_BLK + 626, 256>>>(ei, w, x);

    dim3 sb(NQ, 16);                               // 256 threads, 16 nodes/block
    k_spmv1<<<NN / 16, sb>>>(W1, b1, W2);
    k_spmv2<<<NN / 16, sb>>>(b2);

    dim3 tb(32, 8);
    dim3 tg((NN + 31) / 32, NG / 32);
    k_out<<<tg, tb>>>(x, mask, out);
}

// round 10
// speedup vs baseline: 1.1399x; 1.0091x over previous
#include <cuda_runtime.h>

// Problem constants (fixed shapes from setup_inputs)
#define NN 10000          // nodes
#define NE 160000         // edges
#define NG 64             // replicas B*S = 2*32
#define NQ 16             // NG/4 float4 lanes per node
#define NH 32             // hidden dim

// ---- device scratch (static, no allocations; zero-init at module load) ----
__device__ float  g_deg[NN];        // zeroed by k_spmv2 of previous invocation
__device__ int    g_cnt[NN];        // histogram -> absolute scatter cursor
__device__ float  g_dinv[NN];
__device__ int    g_rowptr[NN + 1];
__device__ int2   g_cv[NE];         // packed {col, w bits}
__device__ float4 g_xT[NN * NQ];    // dinv-scaled x, node-major [n][g]
__device__ float4 g_tT[NN * NQ];    // dinv-scaled layer-1 output
__device__ float4 g_oT[NN * NQ];    // layer-2 output
__device__ float  g_P, g_M;         // collapsed-MLP slopes (b1 == 0 fast path)
__device__ int    g_fast;           // 1 iff all b1[h] == 0

// ------------------------------------------------------------ degree + count
// 8 edges/thread, vector loads. Requires g_deg/g_cnt pre-zeroed.
__global__ void k_degcnt(const int* __restrict__ ei, const float* __restrict__ w) {
    int e8 = blockIdx.x * blockDim.x + threadIdx.x;
    if (e8 >= NE / 8) return;
    const int4*   dp = (const int4*)(ei + NE) + e8 * 2;
    const float4* wp = (const float4*)w + e8 * 2;
    int4   d0 = dp[0], d1 = dp[1];
    float4 v0 = wp[0], v1 = wp[1];
    atomicAdd(&g_deg[d0.x], v0.x); atomicAdd(&g_cnt[d0.x], 1);
    atomicAdd(&g_deg[d0.y], v0.y); atomicAdd(&g_cnt[d0.y], 1);
    atomicAdd(&g_deg[d0.z], v0.z); atomicAdd(&g_cnt[d0.z], 1);
    atomicAdd(&g_deg[d0.w], v0.w); atomicAdd(&g_cnt[d0.w], 1);
    atomicAdd(&g_deg[d1.x], v1.x); atomicAdd(&g_cnt[d1.x], 1);
    atomicAdd(&g_deg[d1.y], v1.y); atomicAdd(&g_cnt[d1.y], 1);
    atomicAdd(&g_deg[d1.z], v1.z); atomicAdd(&g_cnt[d1.z], 1);
    atomicAdd(&g_deg[d1.w], v1.w); atomicAdd(&g_cnt[d1.w], 1);
}

// ------------------------------------------------- dinv + scan (single block)
// Also computes the collapsed-MLP constants P, M and the b1==0 flag.
__global__ void __launch_bounds__(1024) k_scan(const float* __restrict__ W1,
                                               const float* __restrict__ b1,
                                               const float* __restrict__ W2) {
    const int tid  = threadIdx.x;
    const int lane = tid & 31;
    const int wid  = tid >> 5;

    if (tid == 0) {
        float P = 0.f, M = 0.f;
        int fast = 1;
        for (int h = 0; h < NH; h++) {
            if (b1[h] != 0.0f) fast = 0;
            float p = W1[h] * W2[h];
            if (W1[h] > 0.0f) P += p; else M += p;
        }
        g_P = P; g_M = M; g_fast = fast;
    }

    for (int i = tid; i < NN; i += 1024)
        g_dinv[i] = rsqrtf(g_deg[i] + 1.0f);

    const int CH = 10;                 // 1024*10 >= 10000
    int base = tid * CH;
    int cnt[CH];
    int sum = 0;
#pragma unroll
    for (int i = 0; i < CH; i++) {
        int idx = base + i;
        cnt[i] = (idx < NN) ? g_cnt[idx] : 0;
        sum += cnt[i];
    }

    int incl = sum;
#pragma unroll
    for (int o = 1; o < 32; o <<= 1) {
        int v = __shfl_up_sync(0xFFFFFFFFu, incl, o);
        if (lane >= o) incl += v;
    }

    __shared__ int warpsum[32];
    if (lane == 31) warpsum[wid] = incl;
    __syncthreads();
    if (wid == 0) {
        int s = warpsum[lane];
#pragma unroll
        for (int o = 1; o < 32; o <<= 1) {
            int u = __shfl_up_sync(0xFFFFFFFFu, s, o);
            if (lane >= o) s += u;
        }
        warpsum[lane] = s;
    }
    __syncthreads();

    int run = (wid ? warpsum[wid - 1] : 0) + (incl - sum);
#pragma unroll
    for (int i = 0; i < CH; i++) {
        int idx = base + i;
        if (idx < NN) {
            g_rowptr[idx] = run;
            g_cnt[idx]    = run;       // absolute cursor for k_build
            run += cnt[i];
        }
    }
    if (tid == 0) g_rowptr[NN] = NE;
}

// --------------------------------------- fused: CSR scatter + scaled transpose
#define BUILD_BLK 157                  // ceil(40000/256)
__global__ void k_build_xpose(const int* __restrict__ ei, const float* __restrict__ w,
                              const float* __restrict__ x) {
    if (blockIdx.x < BUILD_BLK) {
        int e4 = blockIdx.x * blockDim.x + threadIdx.x;
        if (e4 >= NE / 4) return;
        int4   s = ((const int4*)ei)[e4];
        int4   d = ((const int4*)(ei + NE))[e4];
        float4 v = ((const float4*)w)[e4];
        int i0 = atomicAdd(&g_cnt[d.x], 1);
        int i1 = atomicAdd(&g_cnt[d.y], 1);
        int i2 = atomicAdd(&g_cnt[d.z], 1);
        int i3 = atomicAdd(&g_cnt[d.w], 1);
        g_cv[i0] = make_int2(s.x, __float_as_int(v.x));
        g_cv[i1] = make_int2(s.y, __float_as_int(v.y));
        g_cv[i2] = make_int2(s.z, __float_as_int(v.z));
        g_cv[i3] = make_int2(s.w, __float_as_int(v.w));
    } else {
        __shared__ float tile[32][33];
        int bx  = blockIdx.x - BUILD_BLK;   // 0..625
        int n0  = (bx % 313) * 32;
        int g0  = (bx / 313) * 32;
        int tx  = threadIdx.x & 31;
        int ty  = threadIdx.x >> 5;         // 0..7
        float* xT = (float*)g_xT;
        for (int r = ty; r < 32; r += 8) {
            int g = g0 + r, n = n0 + tx;
            if (n < NN) tile[r][tx] = x[g * NN + n];
        }
        __syncthreads();
        for (int r = ty; r < 32; r += 8) {
            int n = n0 + r, g = g0 + tx;
            if (n < NN) xT[n * NG + g] = g_dinv[n] * tile[tx][r];
        }
    }
}

__device__ __forceinline__ float4 f4fma(float s, float4 a, float4 acc) {
    acc.x = fmaf(s, a.x, acc.x);
    acc.y = fmaf(s, a.y, acc.y);
    acc.z = fmaf(s, a.z, acc.z);
    acc.w = fmaf(s, a.w, acc.w);
    return acc;
}

// unroll-8 gather row-sum over src, 8 outstanding 16B loads
__device__ __forceinline__ float4 row_accum(const float4* __restrict__ base,
                                            int beg, int end, int q, float4 acc) {
    int j = beg;
#pragma unroll 1
    for (; j + 8 <= end; j += 8) {
        int2 c0 = g_cv[j],     c1 = g_cv[j + 1], c2 = g_cv[j + 2], c3 = g_cv[j + 3];
        int2 c4 = g_cv[j + 4], c5 = g_cv[j + 5], c6 = g_cv[j + 6], c7 = g_cv[j + 7];
        float4 a0 = base[c0.x * NQ + q], a1 = base[c1.x * NQ + q];
        float4 a2 = base[c2.x * NQ + q], a3 = base[c3.x * NQ + q];
        float4 a4 = base[c4.x * NQ + q], a5 = base[c5.x * NQ + q];
        float4 a6 = base[c6.x * NQ + q], a7 = base[c7.x * NQ + q];
        acc = f4fma(__int_as_float(c0.y), a0, acc);
        acc = f4fma(__int_as_float(c1.y), a1, acc);
        acc = f4fma(__int_as_float(c2.y), a2, acc);
        acc = f4fma(__int_as_float(c3.y), a3, acc);
        acc = f4fma(__int_as_float(c4.y), a4, acc);
        acc = f4fma(__int_as_float(c5.y), a5, acc);
        acc = f4fma(__int_as_float(c6.y), a6, acc);
        acc = f4fma(__int_as_float(c7.y), a7, acc);
    }
#pragma unroll 1
    for (; j < end; j++) {
        int2 c = g_cv[j];
        acc = f4fma(__int_as_float(c.y), base[c.x * NQ + q], acc);
    }
    return acc;
}

// ------------------------------------------- SpMV pass 1 + collapsed MLP
__global__ void __launch_bounds__(256) k_spmv1(const float* __restrict__ W1,
                                               const float* __restrict__ b1,
                                               const float* __restrict__ W2) {
    __shared__ float sw1[NH], sb1[NH], sw2[NH];
    int t = threadIdx.y * NQ + threadIdx.x;
    if (t < NH) { sw1[t] = W1[t]; sb1[t] = b1[t]; sw2[t] = W2[t]; }
    __syncthreads();

    int q = threadIdx.x;
    int n = blockIdx.x * blockDim.y + threadIdx.y;
    if (n >= NN) return;

    float4 acc = row_accum(g_xT, g_rowptr[n], g_rowptr[n + 1], q,
                           g_xT[n * NQ + q]);   // self-loop term pre-scaled

    float dv = g_dinv[n];
    float4 s = make_float4(dv * acc.x, dv * acc.y, dv * acc.z, dv * acc.w);
    float4 res;
    if (g_fast) {
        float P = g_P, M = g_M;
        res.x = s.x * (s.x > 0.f ? P : M);
        res.y = s.y * (s.y > 0.f ? P : M);
        res.z = s.z * (s.z > 0.f ? P : M);
        res.w = s.w * (s.w > 0.f ? P : M);
    } else {
        res = make_float4(0.f, 0.f, 0.f, 0.f);
#pragma unroll
        for (int h = 0; h < NH; h++) {
            float w1 = sw1[h], bb = sb1[h], w2 = sw2[h];
            res.x = fmaf(fmaxf(fmaf(s.x, w1, bb), 0.f), w2, res.x);
            res.y = fmaf(fmaxf(fmaf(s.y, w1, bb), 0.f), w2, res.y);
            res.z = fmaf(fmaxf(fmaf(s.z, w1, bb), 0.f), w2, res.z);
            res.w = fmaf(fmaxf(fmaf(s.w, w1, bb), 0.f), w2, res.w);
        }
    }
    // pre-scale for layer 2: t~ = dinv * t
    g_tT[n * NQ + q] = make_float4(dv * res.x, dv * res.y, dv * res.z, dv * res.w);
}

// ------------------------------------------- SpMV pass 2: out = dinv*acc + b2
// Also re-zeroes g_deg/g_cnt for the next invocation (module load zero-inits).
__global__ void __launch_bounds__(256) k_spmv2(const float* __restrict__ b2) {
    int lin = blockIdx.x * 256 + threadIdx.y * NQ + threadIdx.x;
    if (lin < NN) { g_deg[lin] = 0.0f; g_cnt[lin] = 0; }

    int q = threadIdx.x;
    int n = blockIdx.x * blockDim.y + threadIdx.y;
    if (n >= NN) return;

    float4 acc = row_accum(g_tT, g_rowptr[n], g_rowptr[n + 1], q,
                           g_tT[n * NQ + q]);

    float dv = g_dinv[n], bb = b2[0];
    g_oT[n * NQ + q] = make_float4(fmaf(dv, acc.x, bb), fmaf(dv, acc.y, bb),
                                   fmaf(dv, acc.z, bb), fmaf(dv, acc.w, bb));
}

// ------------------ output transpose + mask merge
__global__ void k_out(const float* __restrict__ x, const int* __restrict__ mask,
                      float* __restrict__ out) {
    __shared__ float tile[32][33];
    int n0 = blockIdx.x * 32;
    int g0 = blockIdx.y * 32;
    const float* oT = (const float*)g_oT;
    for (int r = threadIdx.y; r < 32; r += 8) {
        int n = n0 + r;
        if (n < NN) tile[r][threadIdx.x] = oT[n * NG + g0 + threadIdx.x];
    }
    __syncthreads();
    for (int r = threadIdx.y; r < 32; r += 8) {
        int g = g0 + r;
        int n = n0 + threadIdx.x;
        if (n < NN) {
            int idx = g * NN + n;
            out[idx] = (mask[idx] != 0) ? x[idx] : tile[threadIdx.x][r];
        }
    }
}

extern "C" void kernel_launch(void* const* d_in, const int* in_sizes, int n_in,
                              void* d_out, int out_size) {
    const float* x    = (const float*)d_in[0];
    const int*   mask = (const int*)d_in[1];       // bool materialized as int32
    const int*   ei   = (const int*)d_in[2];       // (2, E)
    const float* w    = (const float*)d_in[3];
    const float* W1   = (const float*)d_in[4];
    const float* b1   = (const float*)d_in[5];
    const float* W2   = (const float*)d_in[6];
    const float* b2   = (const float*)d_in[7];
    float*       out  = (float*)d_out;

    k_degcnt<<<(NE / 8 + 255) / 256, 256>>>(ei, w);
    k_scan  <<<1, 1024>>>(W1, b1, W2);
    k_build_xpose<<<BUILD_BLK + 626, 256>>>(ei, w, x);

    dim3 sb(NQ, 16);                               // 256 threads, 16 nodes/block
    k_spmv1<<<NN / 16, sb>>>(W1, b1, W2);
    k_spmv2<<<NN / 16, sb>>>(b2);

    dim3 tb(32, 8);
    dim3 tg((NN + 31) / 32, NG / 32);
    k_out<<<tg, tb>>>(x, mask, out);
}

// round 12
// speedup vs baseline: 1.1766x; 1.0322x over previous
#include <cuda_runtime.h>

// Problem constants (fixed shapes from setup_inputs)
#define NN 10000          // nodes
#define NE 160000         // edges
#define NG 64             // replicas B*S = 2*32
#define NQ 16             // NG/4 float4 lanes per node
#define NH 32             // hidden dim

// ---- device scratch (static, no allocations; zero-init at module load) ----
__device__ float  g_deg[NN];        // zeroed by k_spmv2 of previous invocation
__device__ int    g_cnt[NN];        // histogram -> absolute scatter cursor
__device__ float  g_dinv[NN];
__device__ int    g_rowptr[NN + 1];
__device__ int2   g_cv[NE];         // packed {col, w bits}
__device__ float4 g_xT[NN * NQ];    // dinv-scaled x, node-major [n][g]
__device__ float4 g_tT[NN * NQ];    // dinv-scaled layer-1 output
__device__ float4 g_oT[NN * NQ];    // layer-2 output
__device__ float  g_P, g_M;         // collapsed-MLP slopes (b1 == 0 fast path)
__device__ int    g_fast;           // 1 iff all b1[h] == 0

// ------------------------------------------------------------ degree + count
// 8 edges/thread, vector loads. Requires g_deg/g_cnt pre-zeroed.
__global__ void k_degcnt(const int* __restrict__ ei, const float* __restrict__ w) {
    int e8 = blockIdx.x * blockDim.x + threadIdx.x;
    if (e8 >= NE / 8) return;
    const int4*   dp = (const int4*)(ei + NE) + e8 * 2;
    const float4* wp = (const float4*)w + e8 * 2;
    int4   d0 = dp[0], d1 = dp[1];
    float4 v0 = wp[0], v1 = wp[1];
    atomicAdd(&g_deg[d0.x], v0.x); atomicAdd(&g_cnt[d0.x], 1);
    atomicAdd(&g_deg[d0.y], v0.y); atomicAdd(&g_cnt[d0.y], 1);
    atomicAdd(&g_deg[d0.z], v0.z); atomicAdd(&g_cnt[d0.z], 1);
    atomicAdd(&g_deg[d0.w], v0.w); atomicAdd(&g_cnt[d0.w], 1);
    atomicAdd(&g_deg[d1.x], v1.x); atomicAdd(&g_cnt[d1.x], 1);
    atomicAdd(&g_deg[d1.y], v1.y); atomicAdd(&g_cnt[d1.y], 1);
    atomicAdd(&g_deg[d1.z], v1.z); atomicAdd(&g_cnt[d1.z], 1);
    atomicAdd(&g_deg[d1.w], v1.w); atomicAdd(&g_cnt[d1.w], 1);
}

// ------------------------------------------------- dinv + scan (single block)
// Also computes the collapsed-MLP constants P, M and the b1==0 flag.
__global__ void __launch_bounds__(1024) k_scan(const float* __restrict__ W1,
                                               const float* __restrict__ b1,
                                               const float* __restrict__ W2) {
    const int tid  = threadIdx.x;
    const int lane = tid & 31;
    const int wid  = tid >> 5;

    if (tid == 0) {
        float P = 0.f, M = 0.f;
        int fast = 1;
        for (int h = 0; h < NH; h++) {
            if (b1[h] != 0.0f) fast = 0;
            float p = W1[h] * W2[h];
            if (W1[h] > 0.0f) P += p; else M += p;
        }
        g_P = P; g_M = M; g_fast = fast;
    }

    for (int i = tid; i < NN; i += 1024)
        g_dinv[i] = rsqrtf(g_deg[i] + 1.0f);

    const int CH = 10;                 // 1024*10 >= 10000
    int base = tid * CH;
    int cnt[CH];
    int sum = 0;
#pragma unroll
    for (int i = 0; i < CH; i++) {
        int idx = base + i;
        cnt[i] = (idx < NN) ? g_cnt[idx] : 0;
        sum += cnt[i];
    }

    int incl = sum;
#pragma unroll
    for (int o = 1; o < 32; o <<= 1) {
        int v = __shfl_up_sync(0xFFFFFFFFu, incl, o);
        if (lane >= o) incl += v;
    }

    __shared__ int warpsum[32];
    if (lane == 31) warpsum[wid] = incl;
    __syncthreads();
    if (wid == 0) {
        int s = warpsum[lane];
#pragma unroll
        for (int o = 1; o < 32; o <<= 1) {
            int u = __shfl_up_sync(0xFFFFFFFFu, s, o);
            if (lane >= o) s += u;
        }
        warpsum[lane] = s;
    }
    __syncthreads();

    int run = (wid ? warpsum[wid - 1] : 0) + (incl - sum);
#pragma unroll
    for (int i = 0; i < CH; i++) {
        int idx = base + i;
        if (idx < NN) {
            g_rowptr[idx] = run;
            g_cnt[idx]    = run;       // absolute cursor for k_build
            run += cnt[i];
        }
    }
    if (tid == 0) g_rowptr[NN] = NE;
}

// --------------------------------------- fused: CSR scatter + scaled transpose
// build: 2 edges/thread (80k threads for more latency hiding on atomics/stores)
#define BUILD_BLK 313                  // ceil(80000/256)
__global__ void k_build_xpose(const int* __restrict__ ei, const float* __restrict__ w,
                              const float* __restrict__ x) {
    if (blockIdx.x < BUILD_BLK) {
        int e2 = blockIdx.x * blockDim.x + threadIdx.x;
        if (e2 >= NE / 2) return;
        int2   s = ((const int2*)ei)[e2];
        int2   d = ((const int2*)(ei + NE))[e2];
        float2 v = ((const float2*)w)[e2];
        int i0 = atomicAdd(&g_cnt[d.x], 1);
        int i1 = atomicAdd(&g_cnt[d.y], 1);
        g_cv[i0] = make_int2(s.x, __float_as_int(v.x));
        g_cv[i1] = make_int2(s.y, __float_as_int(v.y));
    } else {
        __shared__ float tile[32][33];
        int bx  = blockIdx.x - BUILD_BLK;   // 0..625
        int n0  = (bx % 313) * 32;
        int g0  = (bx / 313) * 32;
        int tx  = threadIdx.x & 31;
        int ty  = threadIdx.x >> 5;         // 0..7
        float* xT = (float*)g_xT;
        for (int r = ty; r < 32; r += 8) {
            int g = g0 + r, n = n0 + tx;
            if (n < NN) tile[r][tx] = x[g * NN + n];
        }
        __syncthreads();
        for (int r = ty; r < 32; r += 8) {
            int n = n0 + r, g = g0 + tx;
            if (n < NN) xT[n * NG + g] = g_dinv[n] * tile[tx][r];
        }
    }
}

__device__ __forceinline__ float4 f4fma(float s, float4 a, float4 acc) {
    acc.x = fmaf(s, a.x, acc.x);
    acc.y = fmaf(s, a.y, acc.y);
    acc.z = fmaf(s, a.z, acc.z);
    acc.w = fmaf(s, a.w, acc.w);
    return acc;
}

// unroll-8 gather row-sum over [beg,end), 8 outstanding 16B loads
__device__ __forceinline__ float4 row_accum(const float4* __restrict__ base,
                                            int beg, int end, int q, float4 acc) {
    int j = beg;
#pragma unroll 1
    for (; j + 8 <= end; j += 8) {
        int2 c0 = g_cv[j],     c1 = g_cv[j + 1], c2 = g_cv[j + 2], c3 = g_cv[j + 3];
        int2 c4 = g_cv[j + 4], c5 = g_cv[j + 5], c6 = g_cv[j + 6], c7 = g_cv[j + 7];
        float4 a0 = base[c0.x * NQ + q], a1 = base[c1.x * NQ + q];
        float4 a2 = base[c2.x * NQ + q], a3 = base[c3.x * NQ + q];
        float4 a4 = base[c4.x * NQ + q], a5 = base[c5.x * NQ + q];
        float4 a6 = base[c6.x * NQ + q], a7 = base[c7.x * NQ + q];
        acc = f4fma(__int_as_float(c0.y), a0, acc);
        acc = f4fma(__int_as_float(c1.y), a1, acc);
        acc = f4fma(__int_as_float(c2.y), a2, acc);
        acc = f4fma(__int_as_float(c3.y), a3, acc);
        acc = f4fma(__int_as_float(c4.y), a4, acc);
        acc = f4fma(__int_as_float(c5.y), a5, acc);
        acc = f4fma(__int_as_float(c6.y), a6, acc);
        acc = f4fma(__int_as_float(c7.y), a7, acc);
    }
    if (j + 4 <= end) {
        int2 c0 = g_cv[j], c1 = g_cv[j + 1], c2 = g_cv[j + 2], c3 = g_cv[j + 3];
        float4 a0 = base[c0.x * NQ + q], a1 = base[c1.x * NQ + q];
        float4 a2 = base[c2.x * NQ + q], a3 = base[c3.x * NQ + q];
        acc = f4fma(__int_as_float(c0.y), a0, acc);
        acc = f4fma(__int_as_float(c1.y), a1, acc);
        acc = f4fma(__int_as_float(c2.y), a2, acc);
        acc = f4fma(__int_as_float(c3.y), a3, acc);
        j += 4;
    }
#pragma unroll 1
    for (; j < end; j++) {
        int2 c = g_cv[j];
        acc = f4fma(__int_as_float(c.y), base[c.x * NQ + q], acc);
    }
    return acc;
}

// warp layout: one warp per node. lane = q + 16*half; the two halves split the
// row's edges and combine via shfl_xor(16). 512 threads = 16 nodes/block.
// ------------------------------------------- SpMV pass 1 + collapsed MLP
__global__ void __launch_bounds__(512) k_spmv1(const float* __restrict__ W1,
                                               const float* __restrict__ b1,
                                               const float* __restrict__ W2) {
    __shared__ float sw1[NH], sb1[NH], sw2[NH];
    int t = threadIdx.y * 32 + threadIdx.x;
    if (t < NH) { sw1[t] = W1[t]; sb1[t] = b1[t]; sw2[t] = W2[t]; }
    __syncthreads();

    int lane = threadIdx.x;            // 0..31
    int q    = lane & 15;
    int half = lane >> 4;
    int n = blockIdx.x * blockDim.y + threadIdx.y;
    if (n >= NN) return;

    int beg = g_rowptr[n], end = g_rowptr[n + 1];
    int mid = (beg + end) >> 1;
    float4 acc = half ? make_float4(0.f, 0.f, 0.f, 0.f)
                      : g_xT[n * NQ + q];          // self-loop (pre-scaled)
    acc = row_accum(g_xT, half ? mid : beg, half ? end : mid, q, acc);

    // combine the two halves (partner lane = lane ^ 16, same q)
    acc.x += __shfl_xor_sync(0xFFFFFFFFu, acc.x, 16);
    acc.y += __shfl_xor_sync(0xFFFFFFFFu, acc.y, 16);
    acc.z += __shfl_xor_sync(0xFFFFFFFFu, acc.z, 16);
    acc.w += __shfl_xor_sync(0xFFFFFFFFu, acc.w, 16);
    if (half) return;

    float dv = g_dinv[n];
    float4 s = make_float4(dv * acc.x, dv * acc.y, dv * acc.z, dv * acc.w);
    float4 res;
    if (g_fast) {
        float P = g_P, M = g_M;
        res.x = s.x * (s.x > 0.f ? P : M);
        res.y = s.y * (s.y > 0.f ? P : M);
        res.z = s.z * (s.z > 0.f ? P : M);
        res.w = s.w * (s.w > 0.f ? P : M);
    } else {
        res = make_float4(0.f, 0.f, 0.f, 0.f);
#pragma unroll
        for (int h = 0; h < NH; h++) {
            float w1 = sw1[h], bb = sb1[h], w2 = sw2[h];
            res.x = fmaf(fmaxf(fmaf(s.x, w1, bb), 0.f), w2, res.x);
            res.y = fmaf(fmaxf(fmaf(s.y, w1, bb), 0.f), w2, res.y);
            res.z = fmaf(fmaxf(fmaf(s.z, w1, bb), 0.f), w2, res.z);
            res.w = fmaf(fmaxf(fmaf(s.w, w1, bb), 0.f), w2, res.w);
        }
    }
    // pre-scale for layer 2: t~ = dinv * t
    g_tT[n * NQ + q] = make_float4(dv * res.x, dv * res.y, dv * res.z, dv * res.w);
}

// ------------------------------------------- SpMV pass 2: out = dinv*acc + b2
// Also re-zeroes g_deg/g_cnt for the next invocation (module load zero-inits).
__global__ void __launch_bounds__(512) k_spmv2(const float* __restrict__ b2) {
    int lin = blockIdx.x * 512 + threadIdx.y * 32 + threadIdx.x;
    if (lin < NN) { g_deg[lin] = 0.0f; g_cnt[lin] = 0; }

    int lane = threadIdx.x;
    int q    = lane & 15;
    int half = lane >> 4;
    int n = blockIdx.x * blockDim.y + threadIdx.y;
    if (n >= NN) return;

    int beg = g_rowptr[n], end = g_rowptr[n + 1];
    int mid = (beg + end) >> 1;
    float4 acc = half ? make_float4(0.f, 0.f, 0.f, 0.f)
                      : g_tT[n * NQ + q];
    acc = row_accum(g_tT, half ? mid : beg, half ? end : mid, q, acc);

    acc.x += __shfl_xor_sync(0xFFFFFFFFu, acc.x, 16);
    acc.y += __shfl_xor_sync(0xFFFFFFFFu, acc.y, 16);
    acc.z += __shfl_xor_sync(0xFFFFFFFFu, acc.z, 16);
    acc.w += __shfl_xor_sync(0xFFFFFFFFu, acc.w, 16);
    if (half) return;

    float dv = g_dinv[n], bb = b2[0];
    g_oT[n * NQ + q] = make_float4(fmaf(dv, acc.x, bb), fmaf(dv, acc.y, bb),
                                   fmaf(dv, acc.z, bb), fmaf(dv, acc.w, bb));
}

// ------------------ output transpose + mask merge
__global__ void k_out(const float* __restrict__ x, const int* __restrict__ mask,
                      float* __restrict__ out) {
    __shared__ float tile[32][33];
    int n0 = blockIdx.x * 32;
    int g0 = blockIdx.y * 32;
    const float* oT = (const float*)g_oT;
    for (int r = threadIdx.y; r < 32; r += 8) {
        int n = n0 + r;
        if (n < NN) tile[r][threadIdx.x] = oT[n * NG + g0 + threadIdx.x];
    }
    __syncthreads();
    for (int r = threadIdx.y; r < 32; r += 8) {
        int g = g0 + r;
        int n = n0 + threadIdx.x;
        if (n < NN) {
            int idx = g * NN + n;
            out[idx] = (mask[idx] != 0) ? x[idx] : tile[threadIdx.x][r];
        }
    }
}

extern "C" void kernel_launch(void* const* d_in, const int* in_sizes, int n_in,
                              void* d_out, int out_size) {
    const float* x    = (const float*)d_in[0];
    const int*   mask = (const int*)d_in[1];       // bool materialized as int32
    const int*   ei   = (const int*)d_in[2];       // (2, E)
    const float* w    = (const float*)d_in[3];
    const float* W1   = (const float*)d_in[4];
    const float* b1   = (const float*)d_in[5];
    const float* W2   = (const float*)d_in[6];
    const float* b2   = (const float*)d_in[7];
    float*       out  = (float*)d_out;

    k_degcnt<<<(NE / 8 + 255) / 256, 256>>>(ei, w);
    k_scan  <<<1, 1024>>>(W1, b1, W2);
    k_build_xpose<<<BUILD_BLK + 626, 256>>>(ei, w, x);

    dim3 sb(32, 16);                               // 512 threads, 16 nodes/block
    k_spmv1<<<NN / 16, sb>>>(W1, b1, W2);
    k_spmv2<<<NN / 16, sb>>>(b2);

    dim3 tb(32, 8);
    dim3 tg((NN + 31) / 32, NG / 32);
    k_out<<<tg, tb>>>(x, mask, out);
}